// round 1
// baseline (speedup 1.0000x reference)
#include <cuda_runtime.h>
#include <cstdint>
#include <cstddef>

// Problem constants
#define WNUM  2048
#define NTOK  49
#define CDIM  256
#define HEADS 8
#define MROWS (WNUM * NTOK)   // 100352, divisible by 128

// Static device scratch (no runtime allocation allowed)
__device__ float g_qkv[(size_t)MROWS * 768];      // QKV GEMM output
__device__ float g_attnout[(size_t)MROWS * 256];  // attention output (pre-proj)
__device__ float g_cbias[64 * HEADS * NTOK * NTOK]; // 16*sigmoid(cpb)+mask, per window%64
__device__ float g_tbl[169 * HEADS];              // CPB MLP table
__device__ float g_qkvb[768];                     // fused qkv bias

// ---------------- packed f32x2 helpers (128 FMA/cyc/SM vs 64 scalar) ----------
__device__ __forceinline__ unsigned long long pack2(float x, float y) {
    unsigned long long r;
    asm("mov.b64 %0, {%1, %2};" : "=l"(r) : "f"(x), "f"(y));
    return r;
}
__device__ __forceinline__ void unpack2(unsigned long long v, float& lo, float& hi) {
    asm("mov.b64 {%0, %1}, %2;" : "=f"(lo), "=f"(hi) : "l"(v));
}
__device__ __forceinline__ void ffma2(unsigned long long& d, unsigned long long a,
                                      unsigned long long b) {
    asm("fma.rn.f32x2 %0, %1, %2, %0;" : "+l"(d) : "l"(a), "l"(b));
}

// ---------------- K1a: CPB MLP table + qkv bias vector -----------------------
__global__ void prep_kernel(const float* __restrict__ rct, const float* __restrict__ w1,
                            const float* __restrict__ b1, const float* __restrict__ w2,
                            const float* __restrict__ qb, const float* __restrict__ vb)
{
    const int tid = threadIdx.x;
    for (int c = tid; c < 768; c += 256) {
        float v = 0.f;
        if (c < 256) v = qb[c];
        else if (c >= 512) v = vb[c - 512];
        g_qkvb[c] = v;
    }
    if (tid < 169) {
        const float t0 = rct[tid * 2 + 0];
        const float t1 = rct[tid * 2 + 1];
        float s[8] = {0.f, 0.f, 0.f, 0.f, 0.f, 0.f, 0.f, 0.f};
        for (int j = 0; j < 512; j++) {
            float hval = fmaf(t0, w1[j * 2 + 0], fmaf(t1, w1[j * 2 + 1], b1[j]));
            hval = fmaxf(hval, 0.f);
            #pragma unroll
            for (int h = 0; h < 8; h++) s[h] = fmaf(hval, w2[h * 512 + j], s[h]);
        }
        #pragma unroll
        for (int h = 0; h < 8; h++) g_tbl[tid * 8 + h] = s[h];
    }
}

// ---------------- K1b: combined bias = 16*sigmoid(cpb) + mask ----------------
__global__ void bias_kernel(const int* __restrict__ rpi, const float* __restrict__ mask)
{
    const int i = blockIdx.x * 256 + threadIdx.x;
    if (i >= 64 * 8 * 2401) return;
    const int w   = i / (8 * 2401);
    const int rem = i - w * (8 * 2401);
    const int h   = rem / 2401;
    const int nm  = rem - h * 2401;
    const float t = g_tbl[rpi[nm] * 8 + h];
    const float sig = 16.f / (1.f + __expf(-t));
    g_cbias[i] = sig + mask[w * 2401 + nm];
}

// ---------------- K2/K4: NT SGEMM, 128x128x16, f32x2 packed ------------------
// C[m][n] = sum_k A[m][k]*B[n][k] + bias[n].  K fixed at 256.
// mode 0: A = x (param), bias = g_qkvb, C = g_qkv        (N_ = 768)
// mode 1: A = g_attnout, bias = param, C = d_out (param) (N_ = 256)
__global__ void __launch_bounds__(256) sgemm_nt(
    const float* __restrict__ Ap, const float* __restrict__ Bmat,
    const float* __restrict__ biasp, float* __restrict__ Cp,
    int N_, int mode)
{
    const float* A    = (mode == 0) ? Ap : g_attnout;
    const float* bias = (mode == 0) ? g_qkvb : biasp;
    float*       C    = (mode == 0) ? g_qkv : Cp;

    __shared__ __align__(16) float As[2][16][132];
    __shared__ __align__(16) float Bs[2][16][132];

    const int tid  = threadIdx.x;
    const int m0   = blockIdx.y * 128;
    const int n0   = blockIdx.x * 128;
    const int tx   = tid & 15;
    const int ty   = tid >> 4;
    const int lrow = tid >> 2;        // 0..63
    const int lkq  = (tid & 3) << 2;  // 0,4,8,12

    const float* Ab0 = A    + (size_t)(m0 + lrow) * 256 + lkq;
    const float* Ab1 = Ab0  + (size_t)64 * 256;
    const float* Bb0 = Bmat + (size_t)(n0 + lrow) * 256 + lkq;
    const float* Bb1 = Bb0  + (size_t)64 * 256;

    unsigned long long acc[8][4];
    #pragma unroll
    for (int i = 0; i < 8; i++)
        #pragma unroll
        for (int j = 0; j < 4; j++) acc[i][j] = 0ULL;

    float4 ra0, ra1, rb0, rb1;
    ra0 = *(const float4*)(Ab0);
    ra1 = *(const float4*)(Ab1);
    rb0 = *(const float4*)(Bb0);
    rb1 = *(const float4*)(Bb1);
    #pragma unroll
    for (int c = 0; c < 4; c++) {
        As[0][lkq + c][lrow]      = (&ra0.x)[c];
        As[0][lkq + c][lrow + 64] = (&ra1.x)[c];
        Bs[0][lkq + c][lrow]      = (&rb0.x)[c];
        Bs[0][lkq + c][lrow + 64] = (&rb1.x)[c];
    }
    __syncthreads();

    #pragma unroll 1
    for (int t = 0; t < 16; t++) {
        if (t < 15) {
            const int kk = (t + 1) * 16;
            ra0 = *(const float4*)(Ab0 + kk);
            ra1 = *(const float4*)(Ab1 + kk);
            rb0 = *(const float4*)(Bb0 + kk);
            rb1 = *(const float4*)(Bb1 + kk);
        }
        const int buf = t & 1;
        #pragma unroll
        for (int k = 0; k < 16; k++) {
            const float4* apt = (const float4*)&As[buf][k][ty * 8];
            const float4 a0 = apt[0], a1 = apt[1];
            const ulonglong2* bpt = (const ulonglong2*)&Bs[buf][k][tx * 8];
            const ulonglong2 bq0 = bpt[0], bq1 = bpt[1];
            const unsigned long long bb0 = bq0.x, bb1 = bq0.y, bb2 = bq1.x, bb3 = bq1.y;
            const float av[8] = {a0.x, a0.y, a0.z, a0.w, a1.x, a1.y, a1.z, a1.w};
            #pragma unroll
            for (int i = 0; i < 8; i++) {
                const unsigned long long aa = pack2(av[i], av[i]);
                ffma2(acc[i][0], aa, bb0);
                ffma2(acc[i][1], aa, bb1);
                ffma2(acc[i][2], aa, bb2);
                ffma2(acc[i][3], aa, bb3);
            }
        }
        if (t < 15) {
            const int nbuf = (t + 1) & 1;
            #pragma unroll
            for (int c = 0; c < 4; c++) {
                As[nbuf][lkq + c][lrow]      = (&ra0.x)[c];
                As[nbuf][lkq + c][lrow + 64] = (&ra1.x)[c];
                Bs[nbuf][lkq + c][lrow]      = (&rb0.x)[c];
                Bs[nbuf][lkq + c][lrow + 64] = (&rb1.x)[c];
            }
            __syncthreads();
        }
    }

    float bv[8];
    #pragma unroll
    for (int j = 0; j < 8; j++) bv[j] = bias[n0 + tx * 8 + j];
    #pragma unroll
    for (int i = 0; i < 8; i++) {
        float out[8];
        #pragma unroll
        for (int j = 0; j < 4; j++) {
            float lo, hi;
            unpack2(acc[i][j], lo, hi);
            out[2 * j]     = lo + bv[2 * j];
            out[2 * j + 1] = hi + bv[2 * j + 1];
        }
        float4* cp = (float4*)(C + (size_t)(m0 + ty * 8 + i) * N_ + n0 + tx * 8);
        cp[0] = make_float4(out[0], out[1], out[2], out[3]);
        cp[1] = make_float4(out[4], out[5], out[6], out[7]);
    }
}

// ---------------- K3: fused window attention ---------------------------------
// One CTA per window. smem: qkv tile [49][768] + attn matrix [392][49].
#define NT3 416
__global__ void __launch_bounds__(NT3) attn_kernel(const float* __restrict__ logit_scale)
{
    extern __shared__ __align__(16) float smem[];
    float* qkv_s  = smem;               // 49*768 floats
    float* attn_s = smem + 49 * 768;    // 392*49 floats
    const int b   = blockIdx.x;
    const int tid = threadIdx.x;

    // Load the window's qkv rows (contiguous 150528 B)
    {
        const float4* src = (const float4*)(g_qkv + (size_t)b * (49 * 768));
        float4* dst = (float4*)qkv_s;
        for (int i = tid; i < 49 * 192; i += NT3) dst[i] = src[i];
    }
    __syncthreads();

    // L2-normalize q and k rows; fold per-head logit scale into q
    for (int r = tid; r < 784; r += NT3) {
        const int part = (r >= 392) ? 1 : 0;   // 0 = q, 1 = k
        const int hn = r - part * 392;
        const int h  = hn / 49;
        const int n  = hn - h * 49;
        float4* p4 = (float4*)(qkv_s + n * 768 + part * 256 + h * 32);
        float s0 = 0.f, s1 = 0.f, s2 = 0.f, s3 = 0.f;
        #pragma unroll
        for (int d = 0; d < 8; d++) {
            const float4 v = p4[d];
            s0 = fmaf(v.x, v.x, s0); s1 = fmaf(v.y, v.y, s1);
            s2 = fmaf(v.z, v.z, s2); s3 = fmaf(v.w, v.w, s3);
        }
        float inv = 1.0f / fmaxf(sqrtf((s0 + s1) + (s2 + s3)), 1e-12f);
        if (part == 0)
            inv *= __expf(fminf(logit_scale[h], 4.6051701859880914f)); // log(100)
        #pragma unroll
        for (int d = 0; d < 8; d++) {
            float4 v = p4[d];
            v.x *= inv; v.y *= inv; v.z *= inv; v.w *= inv;
            p4[d] = v;
        }
    }
    __syncthreads();

    // One thread per (head, query-row): logits + softmax + AV
    if (tid < 392) {
        const int h = tid / 49;
        const int n = tid - h * 49;
        const float4* q4 = (const float4*)(qkv_s + n * 768 + h * 32);
        float4 qa[8];
        #pragma unroll
        for (int d = 0; d < 8; d++) qa[d] = q4[d];

        const float* cb = g_cbias + (((size_t)(b & 63) * 8 + h) * 2401) + n * 49;
        float* arow = attn_s + tid * 49;
        float mx = -1e30f;
        for (int m = 0; m < 49; m++) {
            const float4* k4 = (const float4*)(qkv_s + m * 768 + 256 + h * 32);
            float s0 = 0.f, s1 = 0.f, s2 = 0.f, s3 = 0.f;
            #pragma unroll
            for (int d = 0; d < 8; d++) {
                const float4 kv = k4[d];
                s0 = fmaf(qa[d].x, kv.x, s0);
                s1 = fmaf(qa[d].y, kv.y, s1);
                s2 = fmaf(qa[d].z, kv.z, s2);
                s3 = fmaf(qa[d].w, kv.w, s3);
            }
            const float l = ((s0 + s1) + (s2 + s3)) + cb[m];
            arow[m] = l;
            mx = fmaxf(mx, l);
        }
        float ssum = 0.f;
        for (int m = 0; m < 49; m++) {
            const float e = __expf(arow[m] - mx);
            arow[m] = e;
            ssum += e;
        }
        const float rinv = 1.0f / ssum;

        float4 o[8];
        #pragma unroll
        for (int d = 0; d < 8; d++) o[d] = make_float4(0.f, 0.f, 0.f, 0.f);
        for (int m = 0; m < 49; m++) {
            const float pm = arow[m] * rinv;
            const float4* v4 = (const float4*)(qkv_s + m * 768 + 512 + h * 32);
            #pragma unroll
            for (int d = 0; d < 8; d++) {
                const float4 vv = v4[d];
                o[d].x = fmaf(pm, vv.x, o[d].x);
                o[d].y = fmaf(pm, vv.y, o[d].y);
                o[d].z = fmaf(pm, vv.z, o[d].z);
                o[d].w = fmaf(pm, vv.w, o[d].w);
            }
        }
        float4* op = (float4*)(g_attnout + (size_t)(b * 49 + n) * 256 + h * 32);
        #pragma unroll
        for (int d = 0; d < 8; d++) op[d] = o[d];
    }
}

// ---------------- launch -----------------------------------------------------
extern "C" void kernel_launch(void* const* d_in, const int* in_sizes, int n_in,
                              void* d_out, int out_size)
{
    const float* x    = (const float*)d_in[0];
    const float* mask = (const float*)d_in[1];
    const float* qkvw = (const float*)d_in[2];
    const float* qb   = (const float*)d_in[3];
    const float* vb   = (const float*)d_in[4];
    const float* ls   = (const float*)d_in[5];
    const float* w1   = (const float*)d_in[6];
    const float* b1   = (const float*)d_in[7];
    const float* w2   = (const float*)d_in[8];
    const float* pw   = (const float*)d_in[9];
    const float* pb   = (const float*)d_in[10];
    const float* rct  = (const float*)d_in[11];
    const int*   rpi  = (const int*)d_in[12];
    float* out = (float*)d_out;

    const int smem3 = (49 * 768 + 392 * 49) * 4;  // 227360 B
    cudaFuncSetAttribute(attn_kernel, cudaFuncAttributeMaxDynamicSharedMemorySize, smem3);

    prep_kernel<<<1, 256>>>(rct, w1, b1, w2, qb, vb);
    bias_kernel<<<(64 * 8 * 2401 + 255) / 256, 256>>>(rpi, mask);
    sgemm_nt<<<dim3(6, 784), 256>>>(x, qkvw, nullptr, nullptr, 768, 0);
    attn_kernel<<<WNUM, NT3, smem3>>>(ls);
    sgemm_nt<<<dim3(2, 784), 256>>>(nullptr, pw, pb, out, 256, 1);
}